// round 11
// baseline (speedup 1.0000x reference)
#include <cuda_runtime.h>

// DecorrelatedReNorm forward collapses algebraically:
//   W @ W_inv == I  =>  out = (X - running_mean) @ running_W
// Single fused kernel, 16384 blocks x 256 threads, 4 float4 per thread (exact
// cover). Blocks 0..63 compute rmW = rm @ rW and zero-flags of E = rW - I
// (last-block fold -> g_release); they are the lowest block ids => wave-1
// resident => deadlock-free. All blocks FRONT-BATCH their X loads before the
// spin so HBM stays busy during prep. E == 0 (actual buffers) -> pure stream
// out = X - rmW; else dense fallback. __launch_bounds__(256,8) forces the
// 32-reg budget so the streaming path keeps 8 blocks/SM (prep may spill).

#define CFEAT 512
#define TB    64
#define NBT   (CFEAT / TB)        // 8
#define PBLK  64                  // prep blocks (8 rows of rW each)
#define BLK   256
#define AGRID 16384               // NV4 / (4 * BLK); NV4 = 16,777,216
#define STRIDE 4194304            // AGRID * BLK (float4 units), fits in int

__device__ __align__(16) float g_partial[PBLK][CFEAT];
__device__ int                 g_flagpart[PBLK];
__device__ int                 g_flagmask[NBT];
__device__ int                 g_any;
__device__ __align__(16) float g_rmW[CFEAT];
__device__ int                 g_cnt;        // prep fold ticket (fold resets)
__device__ int                 g_release;    // set by fold, cleared at end
__device__ int                 g_done;       // completion ticket (last resets)

__global__ void __launch_bounds__(BLK, 8) fused_kernel(const float* __restrict__ X,
                                                       const float* __restrict__ rm,
                                                       const float* __restrict__ rW,
                                                       float* __restrict__ out) {
    const int b  = blockIdx.x;
    const int t  = threadIdx.x;
    const int i0 = b * BLK + t;              // float4 index, 32-bit safe

    const float4* X4 = reinterpret_cast<const float4*>(X);
    float4*       O4 = reinterpret_cast<float4*>(out);

    // -------- front-batch the 4 X loads (independent of prep) --------
    float4 x0 = __ldcs(&X4[i0]);
    float4 x1 = __ldcs(&X4[i0 + STRIDE]);
    float4 x2 = __ldcs(&X4[i0 + 2 * STRIDE]);
    float4 x3 = __ldcs(&X4[i0 + 3 * STRIDE]);

    if (b < PBLK) {
        // ---------------- prep: partials + flags, last block folds ----------
        int j4 = t & 127;            // float4 column 0..127
        int g  = t >> 7;             // row subgroup 0..1
        int c0 = b * 8 + g * 4;
        int j  = j4 * 4;
        int jb = j >> 6;

        __shared__ float4 sh[128];
        __shared__ int    shmask;
        __shared__ int    is_last;
        if (t == 0) shmask = 0;
        __syncthreads();

        const float4* W4 = reinterpret_cast<const float4*>(rW);
        float4 acc = make_float4(0.f, 0.f, 0.f, 0.f);
        int diff = 0;
        #pragma unroll
        for (int k = 0; k < 4; ++k) {
            int    c   = c0 + k;
            float4 w   = __ldg(&W4[c * (CFEAT / 4) + j4]);
            float  rmc = __ldg(&rm[c]);
            acc.x += rmc * w.x;  acc.y += rmc * w.y;
            acc.z += rmc * w.z;  acc.w += rmc * w.w;
            diff |= (w.x != ((c == j + 0) ? 1.0f : 0.0f));
            diff |= (w.y != ((c == j + 1) ? 1.0f : 0.0f));
            diff |= (w.z != ((c == j + 2) ? 1.0f : 0.0f));
            diff |= (w.w != ((c == j + 3) ? 1.0f : 0.0f));
        }
        if (g == 1) sh[j4] = acc;
        if (diff) atomicOr(&shmask, 1 << jb);   // bitwise: order-independent
        __syncthreads();
        if (g == 0) {
            float4 o = sh[j4];
            acc.x += o.x;  acc.y += o.y;  acc.z += o.z;  acc.w += o.w;
            reinterpret_cast<float4*>(g_partial[b])[j4] = acc;
        }
        if (t == 0) g_flagpart[b] = shmask;
        __threadfence();
        __syncthreads();
        if (t == 0) is_last = (atomicAdd(&g_cnt, 1) == PBLK - 1);
        __syncthreads();

        if (is_last) {               // block-uniform: whole block folds
            __threadfence();
            #pragma unroll
            for (int h = 0; h < 2; ++h) {
                int jj = t + h * BLK;
                float s = 0.0f;
                #pragma unroll 16
                for (int p = 0; p < PBLK; ++p) s += g_partial[p][jj];
                g_rmW[jj] = s;
            }
            if (t < NBT) {
                int m = 0;
                #pragma unroll
                for (int p = t * 8; p < t * 8 + 8; ++p) m |= g_flagpart[p];
                g_flagmask[t] = m;
            }
            int f = (t < PBLK) ? g_flagpart[t] : 0;
            int a = __syncthreads_or(f);
            if (t == 0) g_any = (a != 0);
            __syncthreads();
            __threadfence();
            if (t == 0) {
                g_cnt = 0;                            // fold ticket reset
                *(volatile int*)&g_release = 1;       // release everyone
            }
        }
    }

    // ---- wait for prep results (wave-1 only; later waves pass through) ----
    if (t == 0) {
        while (*(volatile int*)&g_release == 0) __nanosleep(32);
    }
    __syncthreads();
    __threadfence();

    if (!g_any) {
        // stride % 128 == 0 -> thread's feature column fixed; rmW loaded once
        int    j4 = i0 & (CFEAT / 4 - 1);
        float4 r  = *reinterpret_cast<const float4*>(&g_rmW[j4 * 4]);
        float4 o;
        o.x = x0.x - r.x;  o.y = x0.y - r.y;  o.z = x0.z - r.z;  o.w = x0.w - r.w;
        __stcs(&O4[i0], o);
        o.x = x1.x - r.x;  o.y = x1.y - r.y;  o.z = x1.z - r.z;  o.w = x1.w - r.w;
        __stcs(&O4[i0 + STRIDE], o);
        o.x = x2.x - r.x;  o.y = x2.y - r.y;  o.z = x2.z - r.z;  o.w = x2.w - r.w;
        __stcs(&O4[i0 + 2 * STRIDE], o);
        o.x = x3.x - r.x;  o.y = x3.y - r.y;  o.z = x3.z - r.z;  o.w = x3.w - r.w;
        __stcs(&O4[i0 + 3 * STRIDE], o);
    } else {
        // General fallback: out = X - rmW + X @ E over flagged 64-row blocks.
        float4 xs[4] = {x0, x1, x2, x3};
        #pragma unroll
        for (int k = 0; k < 4; ++k) {
            long long i  = (long long)i0 + (long long)k * STRIDE;
            int       j4 = (int)(i & (CFEAT / 4 - 1));
            long long n  = i >> 7;
            int       j  = j4 * 4;
            int       jb = j / TB;

            float4 r = *reinterpret_cast<const float4*>(&g_rmW[j]);
            float4 o;
            o.x = xs[k].x - r.x;  o.y = xs[k].y - r.y;
            o.z = xs[k].z - r.z;  o.w = xs[k].w - r.w;

            const float* xrow = X + n * CFEAT;
            #pragma unroll
            for (int cb = 0; cb < NBT; ++cb) {
                if (!((__ldg(&g_flagmask[cb]) >> jb) & 1)) continue;
                #pragma unroll 4
                for (int ci = 0; ci < TB; ++ci) {
                    int   c  = cb * TB + ci;
                    float xc = xrow[c];
                    float4 w = *reinterpret_cast<const float4*>(&rW[c * CFEAT + j]);
                    o.x += xc * (w.x - ((c == j + 0) ? 1.0f : 0.0f));
                    o.y += xc * (w.y - ((c == j + 1) ? 1.0f : 0.0f));
                    o.z += xc * (w.z - ((c == j + 2) ? 1.0f : 0.0f));
                    o.w += xc * (w.w - ((c == j + 3) ? 1.0f : 0.0f));
                }
            }
            O4[i] = o;
        }
    }

    // ---- reset for the next graph replay: last block clears the flags ----
    __syncthreads();           // whole block has passed the spin
    if (t == 0) {
        if (atomicAdd(&g_done, 1) == AGRID - 1) {   // everyone passed the spin
            g_done = 0;
            *(volatile int*)&g_release = 0;
        }
    }
}

extern "C" void kernel_launch(void* const* d_in, const int* in_sizes, int n_in,
                              void* d_out, int out_size) {
    const float* X  = (const float*)d_in[0];  // [N, 512]
    const float* rm = (const float*)d_in[1];  // [512]
    const float* rW = (const float*)d_in[2];  // [512, 512]
    float* out = (float*)d_out;

    fused_kernel<<<AGRID, BLK>>>(X, rm, rW, out);
}

// round 12
// speedup vs baseline: 1.2282x; 1.2282x over previous
#include <cuda_runtime.h>

// DecorrelatedReNorm forward collapses algebraically:
//   W @ W_inv == I  =>  out = (X - running_mean) @ running_W
// running_W = I + E. prep (64 blocks) computes rmW = rm @ rW and zero-flags of
// E in one fused float4 pass (last-block fold inside the kernel). apply
// streams out = X - rmW with Blackwell 256-bit ld/st (2 x v8.f32 per thread,
// exact cover); dense fallback if E != 0.

#define CFEAT 512
#define TB    64
#define NBT   (CFEAT / TB)        // 8
#define PBLK  64                  // prep blocks (8 rows of rW each)
#define BLK   256
#define NV8   8388608             // out float8 count (131072 * 512 / 8)
#define AGRID 16384               // NV8 / (2 * BLK)
#define STR8  4194304             // AGRID * BLK, float8 units

__device__ __align__(16) float g_partial[PBLK][CFEAT];
__device__ int                 g_flagpart[PBLK];
__device__ int                 g_flagmask[NBT];
__device__ int                 g_any;
__device__ __align__(32) float g_rmW[CFEAT];
__device__ int                 g_cnt;        // zero-init; reset by fold block

// 64 blocks; block b owns rows c in [8b, 8b+8) of rW. One float4 pass builds
// both identity-diff flags and rm-weighted partials; last block folds.
__global__ void __launch_bounds__(BLK) prep_kernel(const float* __restrict__ rm,
                                                   const float* __restrict__ rW) {
    int b  = blockIdx.x;
    int t  = threadIdx.x;
    int j4 = t & 127;            // float4 column 0..127
    int g  = t >> 7;             // row subgroup 0..1
    int c0 = b * 8 + g * 4;
    int j  = j4 * 4;
    int jb = j >> 6;

    __shared__ float4 sh[128];
    __shared__ int    shmask;
    __shared__ int    is_last;
    if (t == 0) shmask = 0;
    __syncthreads();

    const float4* W4 = reinterpret_cast<const float4*>(rW);
    float4 acc = make_float4(0.f, 0.f, 0.f, 0.f);
    int diff = 0;
    #pragma unroll
    for (int k = 0; k < 4; ++k) {
        int    c   = c0 + k;
        float4 w   = __ldg(&W4[c * (CFEAT / 4) + j4]);
        float  rmc = __ldg(&rm[c]);
        acc.x += rmc * w.x;  acc.y += rmc * w.y;
        acc.z += rmc * w.z;  acc.w += rmc * w.w;
        diff |= (w.x != ((c == j + 0) ? 1.0f : 0.0f));
        diff |= (w.y != ((c == j + 1) ? 1.0f : 0.0f));
        diff |= (w.z != ((c == j + 2) ? 1.0f : 0.0f));
        diff |= (w.w != ((c == j + 3) ? 1.0f : 0.0f));
    }
    if (g == 1) sh[j4] = acc;
    if (diff) atomicOr(&shmask, 1 << jb);   // bitwise: order-independent
    __syncthreads();
    if (g == 0) {
        float4 o = sh[j4];
        acc.x += o.x;  acc.y += o.y;  acc.z += o.z;  acc.w += o.w;
        reinterpret_cast<float4*>(g_partial[b])[j4] = acc;
    }
    if (t == 0) g_flagpart[b] = shmask;
    __threadfence();
    __syncthreads();
    if (t == 0) is_last = (atomicAdd(&g_cnt, 1) == PBLK - 1);
    __syncthreads();

    if (is_last) {                // block-uniform branch: whole block folds
        __threadfence();
        #pragma unroll
        for (int h = 0; h < 2; ++h) {
            int jj = t + h * BLK;
            float s = 0.0f;
            #pragma unroll 16
            for (int p = 0; p < PBLK; ++p) s += g_partial[p][jj];
            g_rmW[jj] = s;
        }
        if (t < NBT) {
            int m = 0;
            #pragma unroll
            for (int p = t * 8; p < t * 8 + 8; ++p) m |= g_flagpart[p];
            g_flagmask[t] = m;
        }
        int f = (t < PBLK) ? g_flagpart[t] : 0;
        int a = __syncthreads_or(f);
        if (t == 0) { g_any = (a != 0); g_cnt = 0; }   // reset for next replay
    }
}

// 256-bit vector load/store helpers (sm_100+).
__device__ __forceinline__ void ldg256_cs(const float* p, float* v) {
    asm volatile("ld.global.cs.v8.f32 {%0,%1,%2,%3,%4,%5,%6,%7}, [%8];"
                 : "=f"(v[0]), "=f"(v[1]), "=f"(v[2]), "=f"(v[3]),
                   "=f"(v[4]), "=f"(v[5]), "=f"(v[6]), "=f"(v[7])
                 : "l"(p));
}
__device__ __forceinline__ void stg256_cs(float* p, const float* v) {
    asm volatile("st.global.cs.v8.f32 [%0], {%1,%2,%3,%4,%5,%6,%7,%8};"
                 :: "l"(p), "f"(v[0]), "f"(v[1]), "f"(v[2]), "f"(v[3]),
                    "f"(v[4]), "f"(v[5]), "f"(v[6]), "f"(v[7])
                 : "memory");
}

// Exactly 2 float8 per thread (AGRID*BLK*2 == NV8). Both loads front-batched.
// Stride is a multiple of 64 float8s -> thread's feature column is fixed.
__global__ void __launch_bounds__(BLK) apply_kernel(const float* __restrict__ X,
                                                    const float* __restrict__ rW,
                                                    float* __restrict__ out) {
    const int i0 = blockIdx.x * BLK + threadIdx.x;   // float8 index (32-bit safe)

    float a[8], c[8];
    ldg256_cs(X + (size_t)i0 * 8, a);
    ldg256_cs(X + ((size_t)i0 + STR8) * 8, c);

    int any = g_any;   // uniform
    if (!any) {
        int j = (i0 & 63) * 8;                       // fixed column of this thread
        float r[8];
        #pragma unroll
        for (int k = 0; k < 8; ++k) r[k] = g_rmW[j + k];
        float o[8];
        #pragma unroll
        for (int k = 0; k < 8; ++k) o[k] = a[k] - r[k];
        stg256_cs(out + (size_t)i0 * 8, o);
        #pragma unroll
        for (int k = 0; k < 8; ++k) o[k] = c[k] - r[k];
        stg256_cs(out + ((size_t)i0 + STR8) * 8, o);
        return;
    }

    // General fallback: out = X - rmW + X @ E over flagged 64-row blocks.
    #pragma unroll
    for (int h = 0; h < 2; ++h) {
        long long i8 = (long long)i0 + (long long)h * STR8;   // float8 index
        int       j  = (int)(i8 & 63) * 8;
        long long n  = i8 >> 6;
        int       jb = j / TB;                                // j..j+7 same block
        const float* xin = (h == 0) ? a : c;

        float o[8];
        #pragma unroll
        for (int k = 0; k < 8; ++k) o[k] = xin[k] - g_rmW[j + k];

        const float* xrow = X + n * CFEAT;
        #pragma unroll
        for (int cb = 0; cb < NBT; ++cb) {
            if (!((__ldg(&g_flagmask[cb]) >> jb) & 1)) continue;
            for (int ci = 0; ci < TB; ++ci) {
                int   cc = cb * TB + ci;
                float xc = xrow[cc];
                #pragma unroll
                for (int k = 0; k < 8; ++k) {
                    float w = rW[cc * CFEAT + j + k];
                    o[k] += xc * (w - ((cc == j + k) ? 1.0f : 0.0f));
                }
            }
        }
        #pragma unroll
        for (int k = 0; k < 8; ++k) out[i8 * 8 + k] = o[k];
    }
}

extern "C" void kernel_launch(void* const* d_in, const int* in_sizes, int n_in,
                              void* d_out, int out_size) {
    const float* X  = (const float*)d_in[0];  // [N, 512]
    const float* rm = (const float*)d_in[1];  // [512]
    const float* rW = (const float*)d_in[2];  // [512, 512]
    float* out = (float*)d_out;

    prep_kernel<<<PBLK, BLK>>>(rm, rW);
    apply_kernel<<<AGRID, BLK>>>(X, rW, out);
}

// round 13
// speedup vs baseline: 1.2499x; 1.0176x over previous
#include <cuda_runtime.h>

// DecorrelatedReNorm forward collapses algebraically:
//   W @ W_inv == I  =>  out = (X - running_mean) @ running_W
// running_W = I + E. prep (8 blocks x 1024 threads) computes rmW = rm @ rW and
// per-64-row zero-flags of E in one pass; block b owns flag-block b directly,
// and the last-block fold only reduces 8 partials. apply streams out = X - rmW
// with 256-bit ld/st (2 x v8.f32 per thread, exact cover); dense fallback if
// E != 0.

#define CFEAT 512
#define TB    64
#define NBT   (CFEAT / TB)        // 8
#define PBLK  8                   // prep blocks (64 rows of rW each)
#define PTHR  1024
#define BLK   256
#define NV8   8388608             // out float8 count (131072 * 512 / 8)
#define AGRID 16384               // NV8 / (2 * BLK)
#define STR8  4194304             // AGRID * BLK, float8 units

__device__ __align__(16) float g_partial[PBLK][CFEAT];
__device__ int                 g_flagmask[NBT];   // [cb]: jb bitmask of E!=0
__device__ int                 g_any;
__device__ __align__(32) float g_rmW[CFEAT];
__device__ int                 g_cnt;             // zero-init; reset by fold

// 8 blocks; block b owns rows [64b, 64b+64) of rW == flag row-block b.
__global__ void __launch_bounds__(PTHR) prep_kernel(const float* __restrict__ rm,
                                                    const float* __restrict__ rW) {
    int b   = blockIdx.x;        // 0..7
    int t   = threadIdx.x;       // 0..1023
    int j4  = t & 127;           // float4 column 0..127
    int grp = t >> 7;            // row subgroup 0..7
    int j   = j4 * 4;
    int jb  = j >> 6;
    int c0  = b * TB + grp * 8;

    __shared__ float4 sh[8][128];
    __shared__ int    shmask;
    __shared__ int    is_last;
    if (t == 0) shmask = 0;
    __syncthreads();

    const float4* W4 = reinterpret_cast<const float4*>(rW);
    float4 acc = make_float4(0.f, 0.f, 0.f, 0.f);
    int diff = 0;
    #pragma unroll
    for (int k = 0; k < 8; ++k) {
        int    c   = c0 + k;
        float4 w   = __ldg(&W4[c * (CFEAT / 4) + j4]);
        float  rmc = __ldg(&rm[c]);
        acc.x += rmc * w.x;  acc.y += rmc * w.y;
        acc.z += rmc * w.z;  acc.w += rmc * w.w;
        diff |= (w.x != ((c == j + 0) ? 1.0f : 0.0f));
        diff |= (w.y != ((c == j + 1) ? 1.0f : 0.0f));
        diff |= (w.z != ((c == j + 2) ? 1.0f : 0.0f));
        diff |= (w.w != ((c == j + 3) ? 1.0f : 0.0f));
    }
    sh[grp][j4] = acc;
    if (diff) atomicOr(&shmask, 1 << jb);   // bitwise: order-independent
    __syncthreads();

    if (grp == 0) {
        #pragma unroll
        for (int p = 1; p < 8; ++p) {
            float4 o = sh[p][j4];
            acc.x += o.x;  acc.y += o.y;  acc.z += o.z;  acc.w += o.w;
        }
        reinterpret_cast<float4*>(g_partial[b])[j4] = acc;
    }
    if (t == 0) g_flagmask[b] = shmask;     // block b IS flag row-block b
    __threadfence();
    __syncthreads();
    if (t == 0) is_last = (atomicAdd(&g_cnt, 1) == PBLK - 1);
    __syncthreads();

    if (is_last) {               // block-uniform: fold 8 partials + 8 flags
        __threadfence();
        if (t < CFEAT) {
            float s = 0.0f;
            #pragma unroll
            for (int p = 0; p < PBLK; ++p) s += g_partial[p][t];
            g_rmW[t] = s;
        }
        if (t == 0) {
            int a = 0;
            #pragma unroll
            for (int p = 0; p < NBT; ++p) a |= g_flagmask[p];
            g_any = (a != 0);
            g_cnt = 0;                       // reset for next graph replay
        }
    }
}

// 256-bit vector load/store helpers (sm_100+).
__device__ __forceinline__ void ldg256_cs(const float* p, float* v) {
    asm volatile("ld.global.cs.v8.f32 {%0,%1,%2,%3,%4,%5,%6,%7}, [%8];"
                 : "=f"(v[0]), "=f"(v[1]), "=f"(v[2]), "=f"(v[3]),
                   "=f"(v[4]), "=f"(v[5]), "=f"(v[6]), "=f"(v[7])
                 : "l"(p));
}
__device__ __forceinline__ void stg256_cs(float* p, const float* v) {
    asm volatile("st.global.cs.v8.f32 [%0], {%1,%2,%3,%4,%5,%6,%7,%8};"
                 :: "l"(p), "f"(v[0]), "f"(v[1]), "f"(v[2]), "f"(v[3]),
                    "f"(v[4]), "f"(v[5]), "f"(v[6]), "f"(v[7])
                 : "memory");
}

// Exactly 2 float8 per thread (AGRID*BLK*2 == NV8). Both loads front-batched.
// Stride is a multiple of 64 float8s -> thread's feature column is fixed.
__global__ void __launch_bounds__(BLK) apply_kernel(const float* __restrict__ X,
                                                    const float* __restrict__ rW,
                                                    float* __restrict__ out) {
    const int i0 = blockIdx.x * BLK + threadIdx.x;   // float8 index (32-bit safe)

    float a[8], c[8];
    ldg256_cs(X + (size_t)i0 * 8, a);
    ldg256_cs(X + ((size_t)i0 + STR8) * 8, c);

    int any = g_any;   // uniform
    if (!any) {
        int j = (i0 & 63) * 8;                       // fixed column of this thread
        float r[8];
        #pragma unroll
        for (int k = 0; k < 8; ++k) r[k] = g_rmW[j + k];
        float o[8];
        #pragma unroll
        for (int k = 0; k < 8; ++k) o[k] = a[k] - r[k];
        stg256_cs(out + (size_t)i0 * 8, o);
        #pragma unroll
        for (int k = 0; k < 8; ++k) o[k] = c[k] - r[k];
        stg256_cs(out + ((size_t)i0 + STR8) * 8, o);
        return;
    }

    // General fallback: out = X - rmW + X @ E over flagged 64-row blocks.
    #pragma unroll
    for (int h = 0; h < 2; ++h) {
        long long i8 = (long long)i0 + (long long)h * STR8;   // float8 index
        int       j  = (int)(i8 & 63) * 8;
        long long n  = i8 >> 6;
        int       jb = j / TB;                                // j..j+7 same block
        const float* xin = (h == 0) ? a : c;

        float o[8];
        #pragma unroll
        for (int k = 0; k < 8; ++k) o[k] = xin[k] - g_rmW[j + k];

        const float* xrow = X + n * CFEAT;
        #pragma unroll
        for (int cb = 0; cb < NBT; ++cb) {
            if (!((__ldg(&g_flagmask[cb]) >> jb) & 1)) continue;
            for (int ci = 0; ci < TB; ++ci) {
                int   cc = cb * TB + ci;
                float xc = xrow[cc];
                #pragma unroll
                for (int k = 0; k < 8; ++k) {
                    float w = rW[cc * CFEAT + j + k];
                    o[k] += xc * (w - ((cc == j + k) ? 1.0f : 0.0f));
                }
            }
        }
        #pragma unroll
        for (int k = 0; k < 8; ++k) out[i8 * 8 + k] = o[k];
    }
}

extern "C" void kernel_launch(void* const* d_in, const int* in_sizes, int n_in,
                              void* d_out, int out_size) {
    const float* X  = (const float*)d_in[0];  // [N, 512]
    const float* rm = (const float*)d_in[1];  // [512]
    const float* rW = (const float*)d_in[2];  // [512, 512]
    float* out = (float*)d_out;

    prep_kernel<<<PBLK, PTHR>>>(rm, rW);
    apply_kernel<<<AGRID, BLK>>>(X, rW, out);
}